// round 1
// baseline (speedup 1.0000x reference)
#include <cuda_runtime.h>
#include <cuda_bf16.h>
#include <cstddef>

// ---------------------------------------------------------------------------
// AttentionBlock: GroupNorm -> QKV 1x1conv -> MHSA (8 heads, ch=64) -> proj ->
// residual.  B=16, C=512, N=1024.
// Round 0: fp32 baseline. Tiled SGEMMs + fused flash-attention (no score
// materialization). Scratch in __device__ globals (no allocation).
// ---------------------------------------------------------------------------

#define B_      16
#define C_      512
#define N_      1024
#define HEADS   8
#define CH      64          // C_/HEADS
#define GROUPS  32
#define GSIZE   16          // C_/GROUPS

__device__ float g_xn [(size_t)B_ * C_ * N_];        // 32 MB
__device__ float g_qkv[(size_t)B_ * 3 * C_ * N_];    // 96 MB
__device__ float g_h  [(size_t)B_ * C_ * N_];        // 32 MB

// ---------------------------------------------------------------------------
// Kernel 1: GroupNorm.  One block per (batch, group): 16 ch x 1024 = 16384 el.
// ---------------------------------------------------------------------------
__global__ __launch_bounds__(256) void groupnorm_kernel(
    const float* __restrict__ x, const float* __restrict__ gamma,
    const float* __restrict__ beta, float* __restrict__ xn)
{
    int b = blockIdx.x >> 5;
    int g = blockIdx.x & 31;
    size_t base = ((size_t)b * C_ + g * GSIZE) * N_;
    const float4* xp = (const float4*)(x + base);
    float4* yp = (float4*)(xn + base);
    int tid = threadIdx.x;

    float s = 0.f, ss = 0.f;
    #pragma unroll 4
    for (int i = tid; i < 4096; i += 256) {
        float4 v = xp[i];
        s  += v.x + v.y + v.z + v.w;
        ss += v.x*v.x + v.y*v.y + v.z*v.z + v.w*v.w;
    }
    // block reduce
    #pragma unroll
    for (int o = 16; o; o >>= 1) {
        s  += __shfl_xor_sync(0xffffffffu, s,  o);
        ss += __shfl_xor_sync(0xffffffffu, ss, o);
    }
    __shared__ float red[20];
    int w = tid >> 5;
    if ((tid & 31) == 0) { red[w] = s; red[w + 8] = ss; }
    __syncthreads();
    if (tid == 0) {
        float S = 0.f, SS = 0.f;
        #pragma unroll
        for (int i = 0; i < 8; i++) { S += red[i]; SS += red[i + 8]; }
        float mean = S * (1.f / 16384.f);
        float var  = SS * (1.f / 16384.f) - mean * mean;
        red[16] = mean;
        red[17] = rsqrtf(var + 1e-5f);
    }
    __syncthreads();
    float mean = red[16], rstd = red[17];

    #pragma unroll 4
    for (int i = tid; i < 4096; i += 256) {
        int c = g * GSIZE + (i >> 8);          // 256 float4 per channel
        float gw = gamma[c] * rstd;
        float gb = beta[c] - mean * gw;
        float4 v = xp[i];
        v.x = v.x * gw + gb; v.y = v.y * gw + gb;
        v.z = v.z * gw + gb; v.w = v.w * gw + gb;
        yp[i] = v;
    }
}

// ---------------------------------------------------------------------------
// Kernel 2/4: SGEMM  out[b,m,n] = sum_k W[m,k] * X[b,k,n] + bias[m] (+res)
// BM=BN=128, BK=16, 256 threads, 8x8 microtile. N fixed = 1024.
// ---------------------------------------------------------------------------
template<bool RES>
__global__ __launch_bounds__(256) void sgemm_kernel(
    const float* __restrict__ W, const float* __restrict__ X,
    const float* __restrict__ bias, const float* __restrict__ res,
    float* __restrict__ out, int M, int K)
{
    __shared__ float Ws[16][128];
    __shared__ float Xs[16][128];

    int m0 = blockIdx.x * 128;
    int n0 = blockIdx.y * 128;
    int bz = blockIdx.z;
    X   += (size_t)bz * K * N_;
    out += (size_t)bz * M * N_;
    if (RES) res += (size_t)bz * M * N_;

    int tid = threadIdx.x;
    int tr = tid >> 4, tc = tid & 15;

    float acc[8][8];
    #pragma unroll
    for (int i = 0; i < 8; i++)
        #pragma unroll
        for (int j = 0; j < 8; j++) acc[i][j] = 0.f;

    for (int k0 = 0; k0 < K; k0 += 16) {
        #pragma unroll
        for (int u = 0; u < 2; u++) {
            int v = tid + u * 256;            // 0..511
            int m = v >> 2;
            int kq = (v & 3) << 2;
            float4 w4 = *(const float4*)&W[(size_t)(m0 + m) * K + k0 + kq];
            Ws[kq + 0][m] = w4.x; Ws[kq + 1][m] = w4.y;
            Ws[kq + 2][m] = w4.z; Ws[kq + 3][m] = w4.w;
        }
        #pragma unroll
        for (int u = 0; u < 2; u++) {
            int v = tid + u * 256;
            int k = v >> 5;
            int nq = (v & 31) << 2;
            *(float4*)&Xs[k][nq] = *(const float4*)&X[(size_t)(k0 + k) * N_ + n0 + nq];
        }
        __syncthreads();
        #pragma unroll
        for (int k = 0; k < 16; k++) {
            float a[8], bv[8];
            *(float4*)&a[0]  = *(float4*)&Ws[k][tr * 8];
            *(float4*)&a[4]  = *(float4*)&Ws[k][tr * 8 + 4];
            *(float4*)&bv[0] = *(float4*)&Xs[k][tc * 8];
            *(float4*)&bv[4] = *(float4*)&Xs[k][tc * 8 + 4];
            #pragma unroll
            for (int i = 0; i < 8; i++)
                #pragma unroll
                for (int j = 0; j < 8; j++)
                    acc[i][j] = fmaf(a[i], bv[j], acc[i][j]);
        }
        __syncthreads();
    }

    #pragma unroll
    for (int i = 0; i < 8; i++) {
        int m = m0 + tr * 8 + i;
        float bb = bias[m];
        size_t ro = (size_t)m * N_ + n0 + tc * 8;
        #pragma unroll
        for (int jq = 0; jq < 2; jq++) {
            float4 r;
            r.x = acc[i][jq*4 + 0] + bb;
            r.y = acc[i][jq*4 + 1] + bb;
            r.z = acc[i][jq*4 + 2] + bb;
            r.w = acc[i][jq*4 + 3] + bb;
            if (RES) {
                float4 rr = *(const float4*)&res[ro + jq*4];
                r.x += rr.x; r.y += rr.y; r.z += rr.z; r.w += rr.w;
            }
            *(float4*)&out[ro + jq*4] = r;
        }
    }
}

// ---------------------------------------------------------------------------
// Kernel 3: fused flash attention.
// grid = (8 q-tiles, 128 heads). 256 threads. TQ=128, kv tile=64, D=64.
// qkv layout per head: q rows [h*192, h*192+64), then k, then v.
// scores *= 1/8  (== (ch^-0.25)^2 applied to q and k).
// ---------------------------------------------------------------------------
#define SS_STRIDE 65
#define PT_STRIDE 132

__global__ __launch_bounds__(256, 1) void attn_kernel(
    const float* __restrict__ qkv, float* __restrict__ hout)
{
    extern __shared__ float sm[];
    float* Qs    = sm;                  // 64 x 128        = 8192
    float* Ks    = Qs + 8192;           // 64 x 64         = 4096
    float* VT    = Ks + 4096;           // 64 s x 64 c     = 4096
    float* Ss    = VT + 4096;           // 128 x 65        = 8320
    float* PT    = Ss + 8320;           // 64 s x 132 t    = 8448
    float* rowm  = PT + 8448;           // 128
    float* rowl  = rowm + 128;          // 128
    float* rowsc = rowl + 128;          // 128

    int tid  = threadIdx.x;
    int qt   = blockIdx.x;
    int head = blockIdx.y;
    int b  = head >> 3;
    int hh = head & 7;
    const float* qb = qkv + ((size_t)b * (3 * C_) + hh * (3 * CH)) * N_;
    const float* kb = qb + (size_t)CH * N_;
    const float* vb = qb + (size_t)2 * CH * N_;
    int t0q = qt * 128;

    // Q tile: Qs[c][t]
    #pragma unroll
    for (int u = 0; u < 8; u++) {
        int i = tid + u * 256;            // 0..2047
        int c = i >> 5;
        int tq = (i & 31) << 2;
        *(float4*)&Qs[c * 128 + tq] = *(const float4*)&qb[(size_t)c * N_ + t0q + tq];
    }
    if (tid < 128) { rowm[tid] = -1e30f; rowl[tid] = 0.f; }

    float oacc[4][8];
    #pragma unroll
    for (int i = 0; i < 4; i++)
        #pragma unroll
        for (int j = 0; j < 8; j++) oacc[i][j] = 0.f;

    const int trS = tid >> 4, tcS = tid & 15;     // S microtile: 8t x 4s
    const int tO  = (tid & 31) << 2;              // O microtile: 4t x 8c
    const int cO  = (tid >> 5) << 3;

    for (int s0 = 0; s0 < N_; s0 += 64) {
        __syncthreads();   // protect Ks/VT/PT reuse from previous iteration
        // K tile: Ks[c][s]
        #pragma unroll
        for (int u = 0; u < 4; u++) {
            int i = tid + u * 256;            // 0..1023
            int c = i >> 4;
            int sq = (i & 15) << 2;
            *(float4*)&Ks[c * 64 + sq] = *(const float4*)&kb[(size_t)c * N_ + s0 + sq];
        }
        // V tile transposed: VT[s][c]  (c spread across warp to avoid smem conflicts)
        #pragma unroll
        for (int u = 0; u < 4; u++) {
            int i = tid + u * 256;
            int c = i & 63;
            int sq = (i >> 6) << 2;
            float4 v4 = *(const float4*)&vb[(size_t)c * N_ + s0 + sq];
            VT[(sq + 0) * 64 + c] = v4.x;
            VT[(sq + 1) * 64 + c] = v4.y;
            VT[(sq + 2) * 64 + c] = v4.z;
            VT[(sq + 3) * 64 + c] = v4.w;
        }
        __syncthreads();

        // S = (Q^T K) / 8   -> Ss[t][s]
        float sacc[8][4];
        #pragma unroll
        for (int i = 0; i < 8; i++)
            #pragma unroll
            for (int j = 0; j < 4; j++) sacc[i][j] = 0.f;
        #pragma unroll 8
        for (int c = 0; c < 64; c++) {
            float a[8], bv[4];
            *(float4*)&a[0]  = *(float4*)&Qs[c * 128 + trS * 8];
            *(float4*)&a[4]  = *(float4*)&Qs[c * 128 + trS * 8 + 4];
            *(float4*)&bv[0] = *(float4*)&Ks[c * 64 + tcS * 4];
            #pragma unroll
            for (int i = 0; i < 8; i++)
                #pragma unroll
                for (int j = 0; j < 4; j++)
                    sacc[i][j] = fmaf(a[i], bv[j], sacc[i][j]);
        }
        #pragma unroll
        for (int i = 0; i < 8; i++)
            #pragma unroll
            for (int j = 0; j < 4; j++)
                Ss[(trS * 8 + i) * SS_STRIDE + tcS * 4 + j] = sacc[i][j] * 0.125f;
        __syncthreads();

        // online softmax per t-row (threads 0..127)
        if (tid < 128) {
            const float* row = Ss + tid * SS_STRIDE;
            float mo = rowm[tid];
            float mx = mo;
            #pragma unroll
            for (int s = 0; s < 64; s++) mx = fmaxf(mx, row[s]);
            float corr = __expf(mo - mx);
            float sum = 0.f;
            #pragma unroll
            for (int s = 0; s < 64; s++) {
                float p = __expf(row[s] - mx);
                sum += p;
                PT[s * PT_STRIDE + tid] = p;
            }
            rowm[tid] = mx;
            rowl[tid] = rowl[tid] * corr + sum;
            rowsc[tid] = corr;
        }
        __syncthreads();

        // O = O*corr + P @ V^T
        float f0 = rowsc[tO + 0], f1 = rowsc[tO + 1];
        float f2 = rowsc[tO + 2], f3 = rowsc[tO + 3];
        #pragma unroll
        for (int j = 0; j < 8; j++) {
            oacc[0][j] *= f0; oacc[1][j] *= f1;
            oacc[2][j] *= f2; oacc[3][j] *= f3;
        }
        #pragma unroll 8
        for (int s = 0; s < 64; s++) {
            float a[4], v[8];
            *(float4*)&a[0] = *(float4*)&PT[s * PT_STRIDE + tO];
            *(float4*)&v[0] = *(float4*)&VT[s * 64 + cO];
            *(float4*)&v[4] = *(float4*)&VT[s * 64 + cO + 4];
            #pragma unroll
            for (int i = 0; i < 4; i++)
                #pragma unroll
                for (int j = 0; j < 8; j++)
                    oacc[i][j] = fmaf(a[i], v[j], oacc[i][j]);
        }
    }

    // write h[b, hh*64 + c, t] = oacc / l
    float linv[4];
    #pragma unroll
    for (int i = 0; i < 4; i++) linv[i] = 1.f / rowl[tO + i];
    float* hb = hout + ((size_t)b * C_ + hh * CH) * N_ + t0q;
    #pragma unroll
    for (int j = 0; j < 8; j++) {
        size_t co = (size_t)(cO + j) * N_;
        #pragma unroll
        for (int i = 0; i < 4; i++)
            hb[co + tO + i] = oacc[i][j] * linv[i];
    }
}

// ---------------------------------------------------------------------------
// launch
// ---------------------------------------------------------------------------
extern "C" void kernel_launch(void* const* d_in, const int* in_sizes, int n_in,
                              void* d_out, int out_size)
{
    const float* x      = (const float*)d_in[0];
    const float* gamma  = (const float*)d_in[1];
    const float* beta   = (const float*)d_in[2];
    const float* w_qkv  = (const float*)d_in[3];
    const float* b_qkv  = (const float*)d_in[4];
    const float* w_proj = (const float*)d_in[5];
    const float* b_proj = (const float*)d_in[6];
    float* out = (float*)d_out;

    void *p_xn, *p_qkv, *p_h;
    cudaGetSymbolAddress(&p_xn,  g_xn);
    cudaGetSymbolAddress(&p_qkv, g_qkv);
    cudaGetSymbolAddress(&p_h,   g_h);
    float* xn  = (float*)p_xn;
    float* qkv = (float*)p_qkv;
    float* h   = (float*)p_h;

    // 1. GroupNorm
    groupnorm_kernel<<<B_ * GROUPS, 256>>>(x, gamma, beta, xn);

    // 2. QKV gemm: (1536 x 512) @ (512 x 1024) per batch
    sgemm_kernel<false><<<dim3(12, 8, B_), 256>>>(w_qkv, xn, b_qkv, nullptr,
                                                  qkv, 3 * C_, C_);

    // 3. fused attention
    const int attn_smem = (8192 + 4096 + 4096 + 8320 + 8448 + 384) * 4;
    cudaFuncSetAttribute(attn_kernel, cudaFuncAttributeMaxDynamicSharedMemorySize,
                         attn_smem);
    attn_kernel<<<dim3(8, B_ * HEADS), 256, attn_smem>>>(qkv, h);

    // 4. proj gemm + bias + residual
    sgemm_kernel<true><<<dim3(4, 8, B_), 256>>>(w_proj, h, b_proj, x,
                                                out, C_, C_);
}

// round 2
// speedup vs baseline: 1.0012x; 1.0012x over previous
#include <cuda_runtime.h>
#include <cuda_bf16.h>
#include <cstddef>

// ---------------------------------------------------------------------------
// AttentionBlock: GroupNorm -> QKV 1x1conv -> MHSA (8 heads, ch=64) -> proj ->
// residual.  B=16, C=512, N=1024.
// Round 0: fp32 baseline. Tiled SGEMMs + fused flash-attention (no score
// materialization). Scratch in __device__ globals (no allocation).
// ---------------------------------------------------------------------------

#define B_      16
#define C_      512
#define N_      1024
#define HEADS   8
#define CH      64          // C_/HEADS
#define GROUPS  32
#define GSIZE   16          // C_/GROUPS

__device__ float g_xn [(size_t)B_ * C_ * N_];        // 32 MB
__device__ float g_qkv[(size_t)B_ * 3 * C_ * N_];    // 96 MB
__device__ float g_h  [(size_t)B_ * C_ * N_];        // 32 MB

// ---------------------------------------------------------------------------
// Kernel 1: GroupNorm.  One block per (batch, group): 16 ch x 1024 = 16384 el.
// ---------------------------------------------------------------------------
__global__ __launch_bounds__(256) void groupnorm_kernel(
    const float* __restrict__ x, const float* __restrict__ gamma,
    const float* __restrict__ beta, float* __restrict__ xn)
{
    int b = blockIdx.x >> 5;
    int g = blockIdx.x & 31;
    size_t base = ((size_t)b * C_ + g * GSIZE) * N_;
    const float4* xp = (const float4*)(x + base);
    float4* yp = (float4*)(xn + base);
    int tid = threadIdx.x;

    float s = 0.f, ss = 0.f;
    #pragma unroll 4
    for (int i = tid; i < 4096; i += 256) {
        float4 v = xp[i];
        s  += v.x + v.y + v.z + v.w;
        ss += v.x*v.x + v.y*v.y + v.z*v.z + v.w*v.w;
    }
    // block reduce
    #pragma unroll
    for (int o = 16; o; o >>= 1) {
        s  += __shfl_xor_sync(0xffffffffu, s,  o);
        ss += __shfl_xor_sync(0xffffffffu, ss, o);
    }
    __shared__ float red[20];
    int w = tid >> 5;
    if ((tid & 31) == 0) { red[w] = s; red[w + 8] = ss; }
    __syncthreads();
    if (tid == 0) {
        float S = 0.f, SS = 0.f;
        #pragma unroll
        for (int i = 0; i < 8; i++) { S += red[i]; SS += red[i + 8]; }
        float mean = S * (1.f / 16384.f);
        float var  = SS * (1.f / 16384.f) - mean * mean;
        red[16] = mean;
        red[17] = rsqrtf(var + 1e-5f);
    }
    __syncthreads();
    float mean = red[16], rstd = red[17];

    #pragma unroll 4
    for (int i = tid; i < 4096; i += 256) {
        int c = g * GSIZE + (i >> 8);          // 256 float4 per channel
        float gw = gamma[c] * rstd;
        float gb = beta[c] - mean * gw;
        float4 v = xp[i];
        v.x = v.x * gw + gb; v.y = v.y * gw + gb;
        v.z = v.z * gw + gb; v.w = v.w * gw + gb;
        yp[i] = v;
    }
}

// ---------------------------------------------------------------------------
// Kernel 2/4: SGEMM  out[b,m,n] = sum_k W[m,k] * X[b,k,n] + bias[m] (+res)
// BM=BN=128, BK=16, 256 threads, 8x8 microtile. N fixed = 1024.
// ---------------------------------------------------------------------------
template<bool RES>
__global__ __launch_bounds__(256) void sgemm_kernel(
    const float* __restrict__ W, const float* __restrict__ X,
    const float* __restrict__ bias, const float* __restrict__ res,
    float* __restrict__ out, int M, int K)
{
    __shared__ float Ws[16][128];
    __shared__ float Xs[16][128];

    int m0 = blockIdx.x * 128;
    int n0 = blockIdx.y * 128;
    int bz = blockIdx.z;
    X   += (size_t)bz * K * N_;
    out += (size_t)bz * M * N_;
    if (RES) res += (size_t)bz * M * N_;

    int tid = threadIdx.x;
    int tr = tid >> 4, tc = tid & 15;

    float acc[8][8];
    #pragma unroll
    for (int i = 0; i < 8; i++)
        #pragma unroll
        for (int j = 0; j < 8; j++) acc[i][j] = 0.f;

    for (int k0 = 0; k0 < K; k0 += 16) {
        #pragma unroll
        for (int u = 0; u < 2; u++) {
            int v = tid + u * 256;            // 0..511
            int m = v >> 2;
            int kq = (v & 3) << 2;
            float4 w4 = *(const float4*)&W[(size_t)(m0 + m) * K + k0 + kq];
            Ws[kq + 0][m] = w4.x; Ws[kq + 1][m] = w4.y;
            Ws[kq + 2][m] = w4.z; Ws[kq + 3][m] = w4.w;
        }
        #pragma unroll
        for (int u = 0; u < 2; u++) {
            int v = tid + u * 256;
            int k = v >> 5;
            int nq = (v & 31) << 2;
            *(float4*)&Xs[k][nq] = *(const float4*)&X[(size_t)(k0 + k) * N_ + n0 + nq];
        }
        __syncthreads();
        #pragma unroll
        for (int k = 0; k < 16; k++) {
            float a[8], bv[8];
            *(float4*)&a[0]  = *(float4*)&Ws[k][tr * 8];
            *(float4*)&a[4]  = *(float4*)&Ws[k][tr * 8 + 4];
            *(float4*)&bv[0] = *(float4*)&Xs[k][tc * 8];
            *(float4*)&bv[4] = *(float4*)&Xs[k][tc * 8 + 4];
            #pragma unroll
            for (int i = 0; i < 8; i++)
                #pragma unroll
                for (int j = 0; j < 8; j++)
                    acc[i][j] = fmaf(a[i], bv[j], acc[i][j]);
        }
        __syncthreads();
    }

    #pragma unroll
    for (int i = 0; i < 8; i++) {
        int m = m0 + tr * 8 + i;
        float bb = bias[m];
        size_t ro = (size_t)m * N_ + n0 + tc * 8;
        #pragma unroll
        for (int jq = 0; jq < 2; jq++) {
            float4 r;
            r.x = acc[i][jq*4 + 0] + bb;
            r.y = acc[i][jq*4 + 1] + bb;
            r.z = acc[i][jq*4 + 2] + bb;
            r.w = acc[i][jq*4 + 3] + bb;
            if (RES) {
                float4 rr = *(const float4*)&res[ro + jq*4];
                r.x += rr.x; r.y += rr.y; r.z += rr.z; r.w += rr.w;
            }
            *(float4*)&out[ro + jq*4] = r;
        }
    }
}

// ---------------------------------------------------------------------------
// Kernel 3: fused flash attention.
// grid = (8 q-tiles, 128 heads). 256 threads. TQ=128, kv tile=64, D=64.
// qkv layout per head: q rows [h*192, h*192+64), then k, then v.
// scores *= 1/8  (== (ch^-0.25)^2 applied to q and k).
// ---------------------------------------------------------------------------
#define SS_STRIDE 65
#define PT_STRIDE 132

__global__ __launch_bounds__(256, 1) void attn_kernel(
    const float* __restrict__ qkv, float* __restrict__ hout)
{
    extern __shared__ float sm[];
    float* Qs    = sm;                  // 64 x 128        = 8192
    float* Ks    = Qs + 8192;           // 64 x 64         = 4096
    float* VT    = Ks + 4096;           // 64 s x 64 c     = 4096
    float* Ss    = VT + 4096;           // 128 x 65        = 8320
    float* PT    = Ss + 8320;           // 64 s x 132 t    = 8448
    float* rowm  = PT + 8448;           // 128
    float* rowl  = rowm + 128;          // 128
    float* rowsc = rowl + 128;          // 128

    int tid  = threadIdx.x;
    int qt   = blockIdx.x;
    int head = blockIdx.y;
    int b  = head >> 3;
    int hh = head & 7;
    const float* qb = qkv + ((size_t)b * (3 * C_) + hh * (3 * CH)) * N_;
    const float* kb = qb + (size_t)CH * N_;
    const float* vb = qb + (size_t)2 * CH * N_;
    int t0q = qt * 128;

    // Q tile: Qs[c][t]
    #pragma unroll
    for (int u = 0; u < 8; u++) {
        int i = tid + u * 256;            // 0..2047
        int c = i >> 5;
        int tq = (i & 31) << 2;
        *(float4*)&Qs[c * 128 + tq] = *(const float4*)&qb[(size_t)c * N_ + t0q + tq];
    }
    if (tid < 128) { rowm[tid] = -1e30f; rowl[tid] = 0.f; }

    float oacc[4][8];
    #pragma unroll
    for (int i = 0; i < 4; i++)
        #pragma unroll
        for (int j = 0; j < 8; j++) oacc[i][j] = 0.f;

    const int trS = tid >> 4, tcS = tid & 15;     // S microtile: 8t x 4s
    const int tO  = (tid & 31) << 2;              // O microtile: 4t x 8c
    const int cO  = (tid >> 5) << 3;

    for (int s0 = 0; s0 < N_; s0 += 64) {
        __syncthreads();   // protect Ks/VT/PT reuse from previous iteration
        // K tile: Ks[c][s]
        #pragma unroll
        for (int u = 0; u < 4; u++) {
            int i = tid + u * 256;            // 0..1023
            int c = i >> 4;
            int sq = (i & 15) << 2;
            *(float4*)&Ks[c * 64 + sq] = *(const float4*)&kb[(size_t)c * N_ + s0 + sq];
        }
        // V tile transposed: VT[s][c]  (c spread across warp to avoid smem conflicts)
        #pragma unroll
        for (int u = 0; u < 4; u++) {
            int i = tid + u * 256;
            int c = i & 63;
            int sq = (i >> 6) << 2;
            float4 v4 = *(const float4*)&vb[(size_t)c * N_ + s0 + sq];
            VT[(sq + 0) * 64 + c] = v4.x;
            VT[(sq + 1) * 64 + c] = v4.y;
            VT[(sq + 2) * 64 + c] = v4.z;
            VT[(sq + 3) * 64 + c] = v4.w;
        }
        __syncthreads();

        // S = (Q^T K) / 8   -> Ss[t][s]
        float sacc[8][4];
        #pragma unroll
        for (int i = 0; i < 8; i++)
            #pragma unroll
            for (int j = 0; j < 4; j++) sacc[i][j] = 0.f;
        #pragma unroll 8
        for (int c = 0; c < 64; c++) {
            float a[8], bv[4];
            *(float4*)&a[0]  = *(float4*)&Qs[c * 128 + trS * 8];
            *(float4*)&a[4]  = *(float4*)&Qs[c * 128 + trS * 8 + 4];
            *(float4*)&bv[0] = *(float4*)&Ks[c * 64 + tcS * 4];
            #pragma unroll
            for (int i = 0; i < 8; i++)
                #pragma unroll
                for (int j = 0; j < 4; j++)
                    sacc[i][j] = fmaf(a[i], bv[j], sacc[i][j]);
        }
        #pragma unroll
        for (int i = 0; i < 8; i++)
            #pragma unroll
            for (int j = 0; j < 4; j++)
                Ss[(trS * 8 + i) * SS_STRIDE + tcS * 4 + j] = sacc[i][j] * 0.125f;
        __syncthreads();

        // online softmax per t-row (threads 0..127)
        if (tid < 128) {
            const float* row = Ss + tid * SS_STRIDE;
            float mo = rowm[tid];
            float mx = mo;
            #pragma unroll
            for (int s = 0; s < 64; s++) mx = fmaxf(mx, row[s]);
            float corr = __expf(mo - mx);
            float sum = 0.f;
            #pragma unroll
            for (int s = 0; s < 64; s++) {
                float p = __expf(row[s] - mx);
                sum += p;
                PT[s * PT_STRIDE + tid] = p;
            }
            rowm[tid] = mx;
            rowl[tid] = rowl[tid] * corr + sum;
            rowsc[tid] = corr;
        }
        __syncthreads();

        // O = O*corr + P @ V^T
        float f0 = rowsc[tO + 0], f1 = rowsc[tO + 1];
        float f2 = rowsc[tO + 2], f3 = rowsc[tO + 3];
        #pragma unroll
        for (int j = 0; j < 8; j++) {
            oacc[0][j] *= f0; oacc[1][j] *= f1;
            oacc[2][j] *= f2; oacc[3][j] *= f3;
        }
        #pragma unroll 8
        for (int s = 0; s < 64; s++) {
            float a[4], v[8];
            *(float4*)&a[0] = *(float4*)&PT[s * PT_STRIDE + tO];
            *(float4*)&v[0] = *(float4*)&VT[s * 64 + cO];
            *(float4*)&v[4] = *(float4*)&VT[s * 64 + cO + 4];
            #pragma unroll
            for (int i = 0; i < 4; i++)
                #pragma unroll
                for (int j = 0; j < 8; j++)
                    oacc[i][j] = fmaf(a[i], v[j], oacc[i][j]);
        }
    }

    // write h[b, hh*64 + c, t] = oacc / l
    float linv[4];
    #pragma unroll
    for (int i = 0; i < 4; i++) linv[i] = 1.f / rowl[tO + i];
    float* hb = hout + ((size_t)b * C_ + hh * CH) * N_ + t0q;
    #pragma unroll
    for (int j = 0; j < 8; j++) {
        size_t co = (size_t)(cO + j) * N_;
        #pragma unroll
        for (int i = 0; i < 4; i++)
            hb[co + tO + i] = oacc[i][j] * linv[i];
    }
}

// ---------------------------------------------------------------------------
// launch
// ---------------------------------------------------------------------------
extern "C" void kernel_launch(void* const* d_in, const int* in_sizes, int n_in,
                              void* d_out, int out_size)
{
    const float* x      = (const float*)d_in[0];
    const float* gamma  = (const float*)d_in[1];
    const float* beta   = (const float*)d_in[2];
    const float* w_qkv  = (const float*)d_in[3];
    const float* b_qkv  = (const float*)d_in[4];
    const float* w_proj = (const float*)d_in[5];
    const float* b_proj = (const float*)d_in[6];
    float* out = (float*)d_out;

    void *p_xn, *p_qkv, *p_h;
    cudaGetSymbolAddress(&p_xn,  g_xn);
    cudaGetSymbolAddress(&p_qkv, g_qkv);
    cudaGetSymbolAddress(&p_h,   g_h);
    float* xn  = (float*)p_xn;
    float* qkv = (float*)p_qkv;
    float* h   = (float*)p_h;

    // 1. GroupNorm
    groupnorm_kernel<<<B_ * GROUPS, 256>>>(x, gamma, beta, xn);

    // 2. QKV gemm: (1536 x 512) @ (512 x 1024) per batch
    sgemm_kernel<false><<<dim3(12, 8, B_), 256>>>(w_qkv, xn, b_qkv, nullptr,
                                                  qkv, 3 * C_, C_);

    // 3. fused attention
    const int attn_smem = (8192 + 4096 + 4096 + 8320 + 8448 + 384) * 4;
    cudaFuncSetAttribute(attn_kernel, cudaFuncAttributeMaxDynamicSharedMemorySize,
                         attn_smem);
    attn_kernel<<<dim3(8, B_ * HEADS), 256, attn_smem>>>(qkv, h);

    // 4. proj gemm + bias + residual
    sgemm_kernel<true><<<dim3(4, 8, B_), 256>>>(w_proj, h, b_proj, x,
                                                out, C_, C_);
}

// round 3
// speedup vs baseline: 2.7830x; 2.7796x over previous
#include <cuda_runtime.h>
#include <cuda_bf16.h>
#include <cstddef>

#define B_      16
#define C_      512
#define N_      1024
#define HEADS   8
#define CH      64
#define GROUPS  32
#define GSIZE   16

__device__ float g_qkv[(size_t)B_ * 3 * C_ * N_];    // 96 MB
__device__ float g_h  [(size_t)B_ * C_ * N_];        // 32 MB
__device__ float g_gw [B_ * C_];
__device__ float g_gb [B_ * C_];

// ---------------------------------------------------------------------------
// helpers
// ---------------------------------------------------------------------------
__device__ __forceinline__ unsigned tf32r(float x) {
    unsigned u;
    asm("cvt.rna.tf32.f32 %0, %1;" : "=r"(u) : "f"(x));
    return u;
}

__device__ __forceinline__ void mma8(float* c, const unsigned* a, const unsigned* b) {
    asm volatile(
        "mma.sync.aligned.m16n8k8.row.col.f32.tf32.tf32.f32 "
        "{%0,%1,%2,%3}, {%4,%5,%6,%7}, {%8,%9}, {%0,%1,%2,%3};"
        : "+f"(c[0]), "+f"(c[1]), "+f"(c[2]), "+f"(c[3])
        : "r"(a[0]), "r"(a[1]), "r"(a[2]), "r"(a[3]), "r"(b[0]), "r"(b[1]));
}

#define CP16(dst, src) asm volatile( \
    "cp.async.cg.shared.global [%0], [%1], 16;" :: "r"(dst), "l"(src))
#define CP_COMMIT() asm volatile("cp.async.commit_group;")
#define CP_WAIT(n)  asm volatile("cp.async.wait_group %0;" :: "n"(n))

// ---------------------------------------------------------------------------
// Kernel 1: GroupNorm statistics only -> per-(b,c) scale/bias
// ---------------------------------------------------------------------------
__global__ __launch_bounds__(256) void groupnorm_stats(
    const float* __restrict__ x, const float* __restrict__ gamma,
    const float* __restrict__ beta, float* __restrict__ gw, float* __restrict__ gb)
{
    int b = blockIdx.x >> 5;
    int g = blockIdx.x & 31;
    size_t base = ((size_t)b * C_ + g * GSIZE) * N_;
    const float4* xp = (const float4*)(x + base);
    int tid = threadIdx.x;

    float s = 0.f, ss = 0.f;
    #pragma unroll 4
    for (int i = tid; i < 4096; i += 256) {
        float4 v = xp[i];
        s  += v.x + v.y + v.z + v.w;
        ss += v.x*v.x + v.y*v.y + v.z*v.z + v.w*v.w;
    }
    #pragma unroll
    for (int o = 16; o; o >>= 1) {
        s  += __shfl_xor_sync(0xffffffffu, s,  o);
        ss += __shfl_xor_sync(0xffffffffu, ss, o);
    }
    __shared__ float red[18];
    int w = tid >> 5;
    if ((tid & 31) == 0) { red[w] = s; red[w + 8] = ss; }
    __syncthreads();
    if (tid == 0) {
        float S = 0.f, SS = 0.f;
        #pragma unroll
        for (int i = 0; i < 8; i++) { S += red[i]; SS += red[i + 8]; }
        float mean = S * (1.f / 16384.f);
        float var  = SS * (1.f / 16384.f) - mean * mean;
        red[16] = mean;
        red[17] = rsqrtf(var + 1e-5f);
    }
    __syncthreads();
    if (tid < GSIZE) {
        int c = g * GSIZE + tid;
        float wv = gamma[c] * red[17];
        gw[b * C_ + c] = wv;
        gb[b * C_ + c] = beta[c] - red[16] * wv;
    }
}

// ---------------------------------------------------------------------------
// Kernel 2/4: tf32 tensor-core GEMM
// out[b,m,n] = sum_k W[m,k] * norm(X[b,k,n]) + bias[m] (+res)
// BM=BN=128, BK=16, 256 threads / 8 warps (2m x 4n), warp tile 64x32.
// ---------------------------------------------------------------------------
template<bool NORM, bool RES>
__global__ __launch_bounds__(256) void gemm_tc(
    const float* __restrict__ W, const float* __restrict__ X,
    const float* __restrict__ bias, const float* __restrict__ res,
    const float* __restrict__ gwv, const float* __restrict__ gbv,
    float* __restrict__ out, int M)
{
    __shared__ unsigned Ws[128 * 20];   // [m][k] stride 20
    __shared__ unsigned Xs[16 * 136];   // [k][n] stride 136
    const int K = 512;

    int m0 = blockIdx.x * 128;
    int n0 = blockIdx.y * 128;
    int bz = blockIdx.z;
    X   += (size_t)bz * K * N_;
    out += (size_t)bz * M * N_;
    if (RES)  res += (size_t)bz * M * N_;
    if (NORM) { gwv += bz * C_; gbv += bz * C_; }

    int tid = threadIdx.x, lane = tid & 31, w = tid >> 5;
    int g = lane >> 2, tig = lane & 3;
    int wm = (w & 1) * 64, wn = (w >> 1) * 32;

    float acc[4][4][4];
    #pragma unroll
    for (int i = 0; i < 4; i++)
        #pragma unroll
        for (int j = 0; j < 4; j++)
            #pragma unroll
            for (int q = 0; q < 4; q++) acc[i][j][q] = 0.f;

    for (int k0 = 0; k0 < K; k0 += 16) {
        #pragma unroll
        for (int u = 0; u < 2; u++) {
            int i = tid + 256 * u;
            int m = i >> 2, kq = (i & 3) << 2;
            float4 v = *(const float4*)&W[(size_t)(m0 + m) * K + k0 + kq];
            uint4 t;
            t.x = tf32r(v.x); t.y = tf32r(v.y); t.z = tf32r(v.z); t.w = tf32r(v.w);
            *(uint4*)&Ws[m * 20 + kq] = t;
        }
        #pragma unroll
        for (int u = 0; u < 2; u++) {
            int i = tid + 256 * u;
            int k = i >> 5, nq = (i & 31) << 2;
            float4 v = *(const float4*)&X[(size_t)(k0 + k) * N_ + n0 + nq];
            if (NORM) {
                int c = k0 + k;
                float a = gwv[c], b2 = gbv[c];
                v.x = fmaf(v.x, a, b2); v.y = fmaf(v.y, a, b2);
                v.z = fmaf(v.z, a, b2); v.w = fmaf(v.w, a, b2);
            }
            uint4 t;
            t.x = tf32r(v.x); t.y = tf32r(v.y); t.z = tf32r(v.z); t.w = tf32r(v.w);
            *(uint4*)&Xs[k * 136 + nq] = t;
        }
        __syncthreads();
        #pragma unroll
        for (int ks = 0; ks < 2; ks++) {
            unsigned a[4][4], b[4][2];
            #pragma unroll
            for (int mt = 0; mt < 4; mt++) {
                int r = wm + mt * 16 + g;
                a[mt][0] = Ws[r * 20 + ks * 8 + tig];
                a[mt][1] = Ws[(r + 8) * 20 + ks * 8 + tig];
                a[mt][2] = Ws[r * 20 + ks * 8 + tig + 4];
                a[mt][3] = Ws[(r + 8) * 20 + ks * 8 + tig + 4];
            }
            #pragma unroll
            for (int nt = 0; nt < 4; nt++) {
                b[nt][0] = Xs[(ks * 8 + tig) * 136 + wn + nt * 8 + g];
                b[nt][1] = Xs[(ks * 8 + tig + 4) * 136 + wn + nt * 8 + g];
            }
            #pragma unroll
            for (int mt = 0; mt < 4; mt++)
                #pragma unroll
                for (int nt = 0; nt < 4; nt++)
                    mma8(acc[mt][nt], a[mt], b[nt]);
        }
        __syncthreads();
    }

    #pragma unroll
    for (int mt = 0; mt < 4; mt++) {
        int r0 = m0 + wm + mt * 16 + g, r1 = r0 + 8;
        float b0v = bias[r0], b1v = bias[r1];
        #pragma unroll
        for (int nt = 0; nt < 4; nt++) {
            int cc = n0 + wn + nt * 8 + 2 * tig;
            float2 v0, v1;
            v0.x = acc[mt][nt][0] + b0v; v0.y = acc[mt][nt][1] + b0v;
            v1.x = acc[mt][nt][2] + b1v; v1.y = acc[mt][nt][3] + b1v;
            if (RES) {
                float2 r = *(const float2*)&res[(size_t)r0 * N_ + cc];
                v0.x += r.x; v0.y += r.y;
                r = *(const float2*)&res[(size_t)r1 * N_ + cc];
                v1.x += r.x; v1.y += r.y;
            }
            *(float2*)&out[(size_t)r0 * N_ + cc] = v0;
            *(float2*)&out[(size_t)r1 * N_ + cc] = v1;
        }
    }
}

// ---------------------------------------------------------------------------
// Kernel 3: fused flash attention, tf32 mma.
// grid (8 q-tiles, 128 heads), 256 threads / 8 warps.
// Each warp owns 16 query rows -> in-register online softmax.
// K/V tiles (64 kv-steps) double-buffered via cp.async.
// ---------------------------------------------------------------------------
__global__ __launch_bounds__(256) void attn_tc(
    const float* __restrict__ qkv, float* __restrict__ hout)
{
    extern __shared__ unsigned smu[];
    unsigned* Qs = smu;                    // [t=128][c] stride 68 (tf32)
    unsigned* Ps = Qs + 128 * 68;          // [t=128][s] stride 68 (tf32)
    unsigned* Ks = Ps + 128 * 68;          // 2 x [c=64][s] stride 72 (raw fp32)
    unsigned* Vs = Ks + 2 * 64 * 72;       // 2 x [c=64][s] stride 68 (raw fp32)
    float* Osf = (float*)Qs;               // epilogue overlay [c=64][t] stride 132

    int tid = threadIdx.x, lane = tid & 31, w = tid >> 5;
    int g = lane >> 2, tig = lane & 3;
    int tb = w * 16;
    int qt = blockIdx.x, head = blockIdx.y;
    int b = head >> 3, hh = head & 7;
    const float* qb = qkv + ((size_t)b * 1536 + hh * 192) * N_;
    const float* kb = qb + (size_t)CH * N_;
    const float* vb = qb + (size_t)2 * CH * N_;
    int t0 = qt * 128;

    unsigned ks_base = (unsigned)__cvta_generic_to_shared(Ks);
    unsigned vs_base = (unsigned)__cvta_generic_to_shared(Vs);

    // prefetch tile 0
    {
        #pragma unroll
        for (int u = 0; u < 4; u++) {
            int i = tid + 256 * u;
            int c = i >> 4, sv = i & 15;
            CP16(ks_base + (c * 72 + 4 * sv) * 4, kb + (size_t)c * N_ + 4 * sv);
            CP16(vs_base + (c * 68 + 4 * sv) * 4, vb + (size_t)c * N_ + 4 * sv);
        }
        CP_COMMIT();
    }

    // Q tile transpose-load (fp32 -> tf32)
    #pragma unroll
    for (int u = 0; u < 8; u++) {
        int i = tid + 256 * u;
        int tv = (i >> 2) & 31;
        int c  = (i & 3) | ((i >> 7) << 2);
        float4 v = *(const float4*)&qb[(size_t)c * N_ + t0 + 4 * tv];
        Qs[(4 * tv + 0) * 68 + c] = tf32r(v.x);
        Qs[(4 * tv + 1) * 68 + c] = tf32r(v.y);
        Qs[(4 * tv + 2) * 68 + c] = tf32r(v.z);
        Qs[(4 * tv + 3) * 68 + c] = tf32r(v.w);
    }

    float m0v = -1e30f, m1v = -1e30f, l0v = 0.f, l1v = 0.f;
    float o[8][4];
    #pragma unroll
    for (int i = 0; i < 8; i++)
        #pragma unroll
        for (int j = 0; j < 4; j++) o[i][j] = 0.f;

    for (int it = 0; it < 16; it++) {
        int bi = it & 1;
        if (it + 1 < 16) {
            int nbi = (it + 1) & 1;
            int s0 = (it + 1) * 64;
            #pragma unroll
            for (int u = 0; u < 4; u++) {
                int i = tid + 256 * u;
                int c = i >> 4, sv = i & 15;
                CP16(ks_base + ((nbi * 64 + c) * 72 + 4 * sv) * 4,
                     kb + (size_t)c * N_ + s0 + 4 * sv);
                CP16(vs_base + ((nbi * 64 + c) * 68 + 4 * sv) * 4,
                     vb + (size_t)c * N_ + s0 + 4 * sv);
            }
            CP_COMMIT();
            CP_WAIT(1);
        } else {
            CP_WAIT(0);
        }
        __syncthreads();

        const unsigned* Kb = Ks + bi * 64 * 72;
        const unsigned* Vb = Vs + bi * 64 * 68;

        // S = (Q K^T) / 8
        float sc[8][4];
        #pragma unroll
        for (int i = 0; i < 8; i++)
            #pragma unroll
            for (int j = 0; j < 4; j++) sc[i][j] = 0.f;

        #pragma unroll
        for (int ks = 0; ks < 8; ks++) {
            unsigned a[4];
            int qr = (tb + g) * 68 + ks * 8 + tig;
            a[0] = Qs[qr];            a[1] = Qs[qr + 8 * 68];
            a[2] = Qs[qr + 4];        a[3] = Qs[qr + 8 * 68 + 4];
            #pragma unroll
            for (int nt = 0; nt < 8; nt++) {
                unsigned bb[2];
                bb[0] = Kb[(ks * 8 + tig) * 72 + nt * 8 + g];
                bb[1] = Kb[(ks * 8 + tig + 4) * 72 + nt * 8 + g];
                mma8(sc[nt], a, bb);
            }
        }

        // online softmax (rows tb+g and tb+g+8; quad shuffle reduce)
        float mx0 = -1e30f, mx1 = -1e30f;
        #pragma unroll
        for (int nt = 0; nt < 8; nt++) {
            sc[nt][0] *= 0.125f; sc[nt][1] *= 0.125f;
            sc[nt][2] *= 0.125f; sc[nt][3] *= 0.125f;
            mx0 = fmaxf(mx0, fmaxf(sc[nt][0], sc[nt][1]));
            mx1 = fmaxf(mx1, fmaxf(sc[nt][2], sc[nt][3]));
        }
        mx0 = fmaxf(mx0, __shfl_xor_sync(0xffffffffu, mx0, 1));
        mx0 = fmaxf(mx0, __shfl_xor_sync(0xffffffffu, mx0, 2));
        mx1 = fmaxf(mx1, __shfl_xor_sync(0xffffffffu, mx1, 1));
        mx1 = fmaxf(mx1, __shfl_xor_sync(0xffffffffu, mx1, 2));
        float mn0 = fmaxf(m0v, mx0), mn1 = fmaxf(m1v, mx1);
        float c0 = __expf(m0v - mn0), c1 = __expf(m1v - mn1);
        m0v = mn0; m1v = mn1;
        float s0a = 0.f, s1a = 0.f;
        #pragma unroll
        for (int nt = 0; nt < 8; nt++) {
            float p0 = __expf(sc[nt][0] - mn0), p1 = __expf(sc[nt][1] - mn0);
            float p2 = __expf(sc[nt][2] - mn1), p3 = __expf(sc[nt][3] - mn1);
            s0a += p0 + p1; s1a += p2 + p3;
            uint2 u0; u0.x = tf32r(p0); u0.y = tf32r(p1);
            uint2 u1; u1.x = tf32r(p2); u1.y = tf32r(p3);
            *(uint2*)&Ps[(tb + g) * 68 + nt * 8 + 2 * tig] = u0;
            *(uint2*)&Ps[(tb + g + 8) * 68 + nt * 8 + 2 * tig] = u1;
        }
        s0a += __shfl_xor_sync(0xffffffffu, s0a, 1);
        s0a += __shfl_xor_sync(0xffffffffu, s0a, 2);
        s1a += __shfl_xor_sync(0xffffffffu, s1a, 1);
        s1a += __shfl_xor_sync(0xffffffffu, s1a, 2);
        l0v = l0v * c0 + s0a;
        l1v = l1v * c1 + s1a;
        #pragma unroll
        for (int nt = 0; nt < 8; nt++) {
            o[nt][0] *= c0; o[nt][1] *= c0;
            o[nt][2] *= c1; o[nt][3] *= c1;
        }
        __syncwarp();

        // O += P @ V^T
        #pragma unroll
        for (int ks = 0; ks < 8; ks++) {
            unsigned a[4];
            int pr = (tb + g) * 68 + ks * 8 + tig;
            a[0] = Ps[pr];            a[1] = Ps[pr + 8 * 68];
            a[2] = Ps[pr + 4];        a[3] = Ps[pr + 8 * 68 + 4];
            #pragma unroll
            for (int nt = 0; nt < 8; nt++) {
                unsigned bb[2];
                bb[0] = Vb[(nt * 8 + g) * 68 + ks * 8 + tig];
                bb[1] = Vb[(nt * 8 + g) * 68 + ks * 8 + tig + 4];
                mma8(o[nt], a, bb);
            }
        }
        __syncthreads();
    }

    // epilogue: normalize, stage via smem, coalesced store
    float il0 = 1.f / l0v, il1 = 1.f / l1v;
    #pragma unroll
    for (int nt = 0; nt < 8; nt++) {
        int cc = nt * 8 + 2 * tig;
        Osf[(cc + 0) * 132 + tb + g]     = o[nt][0] * il0;
        Osf[(cc + 1) * 132 + tb + g]     = o[nt][1] * il0;
        Osf[(cc + 0) * 132 + tb + g + 8] = o[nt][2] * il1;
        Osf[(cc + 1) * 132 + tb + g + 8] = o[nt][3] * il1;
    }
    __syncthreads();
    float* hb = hout + ((size_t)b * C_ + hh * CH) * N_ + t0;
    #pragma unroll
    for (int u = 0; u < 8; u++) {
        int i = tid + 256 * u;
        int c = i >> 5, tv = i & 31;
        *(float4*)&hb[(size_t)c * N_ + 4 * tv] = *(const float4*)&Osf[c * 132 + 4 * tv];
    }
}

// ---------------------------------------------------------------------------
// launch
// ---------------------------------------------------------------------------
extern "C" void kernel_launch(void* const* d_in, const int* in_sizes, int n_in,
                              void* d_out, int out_size)
{
    const float* x      = (const float*)d_in[0];
    const float* gamma  = (const float*)d_in[1];
    const float* beta   = (const float*)d_in[2];
    const float* w_qkv  = (const float*)d_in[3];
    const float* b_qkv  = (const float*)d_in[4];
    const float* w_proj = (const float*)d_in[5];
    const float* b_proj = (const float*)d_in[6];
    float* out = (float*)d_out;

    void *p_qkv, *p_h, *p_gw, *p_gb;
    cudaGetSymbolAddress(&p_qkv, g_qkv);
    cudaGetSymbolAddress(&p_h,   g_h);
    cudaGetSymbolAddress(&p_gw,  g_gw);
    cudaGetSymbolAddress(&p_gb,  g_gb);
    float* qkv = (float*)p_qkv;
    float* h   = (float*)p_h;
    float* gw  = (float*)p_gw;
    float* gb  = (float*)p_gb;

    // 1. GroupNorm stats -> per-(b,c) scale/bias
    groupnorm_stats<<<B_ * GROUPS, 256>>>(x, gamma, beta, gw, gb);

    // 2. QKV gemm with fused groupnorm on X
    gemm_tc<true, false><<<dim3(12, 8, B_), 256>>>(
        w_qkv, x, b_qkv, nullptr, gw, gb, qkv, 3 * C_);

    // 3. fused flash attention (tf32 mma)
    const int attn_smem = (128 * 68 + 128 * 68 + 2 * 64 * 72 + 2 * 64 * 68) * 4;
    cudaFuncSetAttribute(attn_tc, cudaFuncAttributeMaxDynamicSharedMemorySize,
                         attn_smem);
    attn_tc<<<dim3(8, B_ * HEADS), 256, attn_smem>>>(qkv, h);

    // 4. proj gemm + bias + residual
    gemm_tc<false, true><<<dim3(4, 8, B_), 256>>>(
        w_proj, h, b_proj, x, nullptr, nullptr, out, C_);
}